// round 15
// baseline (speedup 1.0000x reference)
#include <cuda_runtime.h>
#include <cuda_bf16.h>
#include <mma.h>
#include <math.h>
#include <stdint.h>

using namespace nvcuda;

#define BTOT 512
#define NMEM 30
#define HW 1024
#define NGTH_ 15

typedef unsigned long long u64;

__device__ __forceinline__ u64 dup2f(float v){u64 r;asm("mov.b64 %0,{%1,%1};":"=l"(r):"f"(v));return r;}
__device__ __forceinline__ void fma2(u64&d,u64 a,u64 b){asm("fma.rn.f32x2 %0,%1,%2,%0;":"+l"(d):"l"(a),"l"(b));}
__device__ __forceinline__ float2 unp2(u64 v){float lo,hi;asm("mov.b64 {%0,%1},%2;":"=f"(lo),"=f"(hi):"l"(v));return make_float2(lo,hi);}

__device__ __nv_bfloat16 g_x1h[(size_t)BTOT*225*64];
__device__ __nv_bfloat16 g_x1l[(size_t)BTOT*225*64];
__device__ __nv_bfloat16 g_wh[2*9*4096];      // [conv][tap][ic][oc] hi
__device__ __nv_bfloat16 g_wl[2*9*4096];      // lo

__device__ __forceinline__ unsigned pack2bf(float a, float b) {
    return (unsigned)__bfloat16_as_ushort(__float2bfloat16(a)) |
           ((unsigned)__bfloat16_as_ushort(__float2bfloat16(b)) << 16);
}

// ---------------------------------------------------------------------------
// Kernel 0: weight prep — w2/w3 -> bf16 hi/lo, tap-major coalesced layout
// ---------------------------------------------------------------------------
__global__ __launch_bounds__(256) void wprep_kernel(
    const float* __restrict__ w2, const float* __restrict__ w3)
{
    int i = blockIdx.x * 256 + threadIdx.x;
    if (i < 2 * 9 * 4096) {
        int conv = i / 36864, r = i - conv * 36864;
        int tap = r >> 12, idx = r & 4095;
        int ic = idx >> 6, oc = idx & 63;
        const float* w = conv ? w3 : w2;
        float v = w[oc * 576 + ic * 9 + tap];
        __nv_bfloat16 h = __float2bfloat16(v);
        g_wh[i] = h;
        g_wl[i] = __float2bfloat16(v - __bfloat162float(h));
    }
}

// ---------------------------------------------------------------------------
// Kernel 1: fused stats (1024 thr, high-MLP) + conv1 -> g_x1h/l (bf16 split)
// ---------------------------------------------------------------------------
__global__ __launch_bounds__(1024) void stats_conv1_kernel(
    const float* __restrict__ ts, const float* __restrict__ ptm,
    const float* __restrict__ pmt, const float* __restrict__ piou,
    const void* __restrict__ mask_raw,
    const float* __restrict__ w1, const float* __restrict__ cb1,
    const float* __restrict__ g1, const float* __restrict__ bb1,
    const float* __restrict__ m1, const float* __restrict__ v1)
{
    const int b = blockIdx.x, tid = threadIdx.x, lane = tid & 31, wid = tid >> 5;
    __shared__ float smI[6528];   // 6 ch x 32 rows x 34 stride
    __shared__ float smW[3456];   // conv1 weights pair layout
    __shared__ float smE[128];    // folded scale/bias
    __shared__ float mf[NMEM], ow[NMEM], pmax[NMEM], warpmax[32], sc[16];

    unsigned int w0 = *(const unsigned int*)mask_raw;
    int mode = (w0 == 1u) ? 1 : ((w0 == 0x3F800000u) ? 2 : 0);

    if (tid == 0) {
        float run = 0.f, ca = 0.f, cg = 0.f, co = 0.f;
        for (int m = 0; m < NMEM; ++m) {
            int idx = b * NMEM + m; float f;
            if (mode == 1)      f = (((const int*)mask_raw)[idx] != 0) ? 1.f : 0.f;
            else if (mode == 2) f = (((const float*)mask_raw)[idx] != 0.f) ? 1.f : 0.f;
            else                f = (((const unsigned char*)mask_raw)[idx] != 0) ? 1.f : 0.f;
            run += f;
            float g = (run - 1.f < (float)NGTH_) ? f : 0.f;
            float o = f - g;
            mf[m] = f; ow[m] = o; ca += f; cg += g; co += o;
        }
        sc[7] = ca; sc[8] = cg; sc[9] = co;
        sc[10] = piou[b];
    }

    {
        float v = ts[(size_t)b * HW + tid];
        #pragma unroll
        for (int off = 16; off > 0; off >>= 1) v = fmaxf(v, __shfl_xor_sync(0xffffffffu, v, off));
        if (lane == 0) warpmax[wid] = v;
    }

    if (wid < NMEM) {
        const float* pr = ptm + (size_t)b * NMEM * HW + (size_t)wid * HW;
        float mx = -INFINITY;
        #pragma unroll
        for (int k = 0; k < 32; ++k) mx = fmaxf(mx, pr[lane + 32 * k]);
        #pragma unroll
        for (int off = 16; off > 0; off >>= 1) mx = fmaxf(mx, __shfl_xor_sync(0xffffffffu, mx, off));
        if (lane == 0) pmax[wid] = mx;
    }
    __syncthreads();

    if (wid == 0) {
        float v = warpmax[lane];
        #pragma unroll
        for (int off = 16; off > 0; off >>= 1) v = fmaxf(v, __shfl_xor_sync(0xffffffffu, v, off));
        if (lane == 0) sc[0] = v;
    }
    if (wid == 1) {
        float v  = (lane < NMEM) ? pmax[lane] : 0.f;
        float fa = (lane < NMEM) ? mf[lane] : 0.f;
        float fo = (lane < NMEM) ? ow[lane] : 0.f;
        float fg = fa - fo;
        float sa = v*fa, ssa = v*v*fa, sg = v*fg, ssg = v*v*fg, so = v*fo, sso = v*v*fo;
        #pragma unroll
        for (int off = 16; off > 0; off >>= 1) {
            sa  += __shfl_xor_sync(0xffffffffu, sa, off);  ssa += __shfl_xor_sync(0xffffffffu, ssa, off);
            sg  += __shfl_xor_sync(0xffffffffu, sg, off);  ssg += __shfl_xor_sync(0xffffffffu, ssg, off);
            so  += __shfl_xor_sync(0xffffffffu, so, off);  sso += __shfl_xor_sync(0xffffffffu, sso, off);
        }
        if (lane == 0) {
            float ca = sc[7], cg = sc[8], co = sc[9];
            float mA = sa / ca; sc[1] = mA; sc[2] = sqrtf(fmaxf(ssa / ca - mA * mA, 0.f));
            float mG = sg / cg; sc[3] = mG; sc[4] = sqrtf(fmaxf(ssg / cg - mG * mG, 0.f));
            float mO = so / co; sc[5] = mO; sc[6] = sqrtf(fmaxf(sso / co - mO * mO, 0.f));
        }
    }
    __syncthreads();

    // per-pixel stats -> smI (stride-34), 1 thread/pixel
    {
        const float* pmtb = pmt + (size_t)b * NMEM * HW + tid;
        const float ca = sc[7], co = sc[9];
        float sa = 0, ssa = 0, sg = 0, ssg = 0, so = 0, sso = 0;
        #pragma unroll
        for (int m = 0; m < NMEM; ++m) {
            float v = pmtb[(size_t)m * HW];
            float fa = mf[m], fo = ow[m];
            sa += v * fa; ssa += v * v * fa;
            if (m < NGTH_) { sg += v; ssg += v * v; }
            so += v * fo; sso += v * v * fo;
        }
        float mA = sa / ca, sA = sqrtf(fmaxf(ssa / ca - mA * mA, 0.f));
        float mG = sg * (1.f / NGTH_), sG = sqrtf(fmaxf(ssg * (1.f / NGTH_) - mG * mG, 0.f));
        float mO = so / co, sO = sqrtf(fmaxf(sso / co - mO * mO, 0.f));
        int base = (tid >> 5) * 34 + (tid & 31);
        smI[0 * 1088 + base] = mA; smI[1 * 1088 + base] = sA;
        smI[2 * 1088 + base] = mG; smI[3 * 1088 + base] = sG;
        smI[4 * 1088 + base] = mO; smI[5 * 1088 + base] = sO;
    }
    for (int i = tid; i < 64 * 6 * 9; i += 1024) {
        int oc = i / 54; int r = i - oc * 54;
        int c = r / 9; int t = r - c * 9;
        smW[((oc >> 1) * 6 + c) * 18 + t * 2 + (oc & 1)] = w1[oc * 126 + (c + 2) * 9 + t];
    }
    if (tid < 64) {
        float cst[8] = {sc[0], sc[10], sc[1], sc[2], sc[3], sc[4], sc[5], sc[6]};
        float extra = 0.f;
        #pragma unroll
        for (int j = 0; j < 8; ++j) {
            int ic = (j < 2) ? j : (j + 6);
            const float* wb = w1 + tid * 126 + ic * 9;
            float s9 = 0.f;
            #pragma unroll
            for (int t = 0; t < 9; ++t) s9 += wb[t];
            extra += cst[j] * s9;
        }
        float s = g1[tid] * rsqrtf(v1[tid] + 1e-5f);
        smE[tid] = s;
        smE[64 + tid] = s * (extra + cb1[tid] - m1[tid]) + bb1[tid];
    }
    __syncthreads();

    // conv1 scalar (validated): 960 items, ONE pass at 1024 threads
    __nv_bfloat16* xoh = g_x1h + (size_t)b * 225 * 64;
    __nv_bfloat16* xol = g_x1l + (size_t)b * 225 * 64;
    if (tid < 960) {
        int it = tid;
        int ocg = it / 60;
        int r = it - ocg * 60;
        int pr = r >> 2, pq = r & 3;
        int x0 = 8 * pq, r0 = 2 * pr;

        u64 acc[2][2][8];
        #pragma unroll
        for (int p = 0; p < 2; ++p)
            #pragma unroll
            for (int e = 0; e < 2; ++e)
                #pragma unroll
                for (int c = 0; c < 8; ++c) acc[p][e][c] = 0ull;

        for (int ch = 0; ch < 6; ++ch) {
            const float* ib = &smI[ch * 1088 + r0 * 34 + x0];
            const u64* wb0 = (const u64*)&smW[((ocg * 2) * 6 + ch) * 18];
            const u64* wb1 = (const u64*)&smW[((ocg * 2 + 1) * 6 + ch) * 18];
            #pragma unroll
            for (int ir = 0; ir < 4; ++ir) {
                u64 d[10];
                #pragma unroll
                for (int q = 0; q < 5; ++q) {
                    float2 a = *(const float2*)(ib + ir * 34 + 2 * q);
                    d[2*q] = dup2f(a.x); d[2*q+1] = dup2f(a.y);
                }
                #pragma unroll
                for (int kx = 0; kx < 3; ++kx) {
                    if (ir <= 2) {
                        u64 wa = wb0[ir*3+kx], wc = wb1[ir*3+kx];
                        #pragma unroll
                        for (int c = 0; c < 8; ++c) { fma2(acc[0][0][c], wa, d[c+kx]); fma2(acc[1][0][c], wc, d[c+kx]); }
                    }
                    if (ir >= 1) {
                        u64 wa = wb0[(ir-1)*3+kx], wc = wb1[(ir-1)*3+kx];
                        #pragma unroll
                        for (int c = 0; c < 8; ++c) { fma2(acc[0][1][c], wa, d[c+kx]); fma2(acc[1][1][c], wc, d[c+kx]); }
                    }
                }
            }
        }
        #pragma unroll
        for (int p = 0; p < 2; ++p) {
            int oc0 = ocg * 4 + 2 * p;
            float s0 = smE[oc0], bi0 = smE[64+oc0];
            float s1 = smE[oc0+1], bi1 = smE[64+oc0+1];
            #pragma unroll
            for (int j = 0; j < 4; ++j) {
                int pt = 4 * pq + j;
                if (pt < 15) {
                    float2 a = unp2(acc[p][0][2*j]), bq = unp2(acc[p][0][2*j+1]);
                    float2 cq = unp2(acc[p][1][2*j]), e = unp2(acc[p][1][2*j+1]);
                    float v0 = fmaxf(fmaxf(fmaxf(s0*a.x+bi0,0.f), fmaxf(s0*bq.x+bi0,0.f)),
                                     fmaxf(fmaxf(s0*cq.x+bi0,0.f), fmaxf(s0*e.x+bi0,0.f)));
                    float v1_ = fmaxf(fmaxf(fmaxf(s1*a.y+bi1,0.f), fmaxf(s1*bq.y+bi1,0.f)),
                                      fmaxf(fmaxf(s1*cq.y+bi1,0.f), fmaxf(s1*e.y+bi1,0.f)));
                    int pos = pr * 15 + pt;
                    __nv_bfloat16 h0 = __float2bfloat16(v0), h1 = __float2bfloat16(v1_);
                    *(unsigned*)&xoh[pos * 64 + oc0] =
                        (unsigned)__bfloat16_as_ushort(h0) | ((unsigned)__bfloat16_as_ushort(h1) << 16);
                    *(unsigned*)&xol[pos * 64 + oc0] =
                        pack2bf(v0 - __bfloat162float(h0), v1_ - __bfloat162float(h1));
                }
            }
        }
    }
}

// ---------------------------------------------------------------------------
// Merged conv2+conv3+conv4 kernel.
// smem (dynamic, bytes):
//   X2h [0, 34560)  X2l [34560, 69120)          (240 rows x 72 x bf16)
//   X3h [69120, 94464)  X3l [94464, 119808)     (176 rows x 72 x bf16)
//   W   [119808, 202752)  (9 taps x 64 x 72 x bf16)
//   sbs [202752, 203776)
// aliases (post-mainloop): conv2 patch @0 (26*2304=59904 <= 69120);
//   conv3 patch @0 (18*2304=41472), x3s @41472 (32912 B, over dead X2/X3 head)
// ---------------------------------------------------------------------------
#define OX2H 0
#define OX2L 34560
#define OX3H 69120
#define OX3L 94464
#define OWB  119808
#define OSBS 202752
#define SMEGA 203776

template<int IN_W>
__device__ __forceinline__ void mma_phaseA(
    const __nv_bfloat16* Xh, const __nv_bfloat16* Xl, const __nv_bfloat16* Wsm,
    int mt, int nh,
    wmma::fragment<wmma::accumulator,16,16,16,float>* P,
    wmma::fragment<wmma::accumulator,16,16,16,float>* Q)
{
    #pragma unroll 1
    for (int tap = 0; tap < 9; ++tap) {
        int toff = (tap / 3) * IN_W + (tap - (tap / 3) * 3);
        const __nv_bfloat16* A0 = Xh + (mt * 16 + toff) * 72;
        const __nv_bfloat16* A1 = Xl + (mt * 16 + toff) * 72;
        const __nv_bfloat16* B = Wsm + (tap * 64) * 72 + nh * 32;
        #pragma unroll
        for (int k = 0; k < 4; ++k) {
            wmma::fragment<wmma::matrix_a, 16, 16, 16, __nv_bfloat16, wmma::row_major> ah, al;
            wmma::load_matrix_sync(ah, A0 + k * 16, 72);
            wmma::load_matrix_sync(al, A1 + k * 16, 72);
            #pragma unroll
            for (int nt = 0; nt < 2; ++nt) {
                wmma::fragment<wmma::matrix_b, 16, 16, 16, __nv_bfloat16, wmma::row_major> bh;
                wmma::load_matrix_sync(bh, B + k * 16 * 72 + nt * 16, 72);
                wmma::mma_sync(P[nt], ah, bh, P[nt]);
                wmma::mma_sync(Q[nt], al, bh, Q[nt]);
            }
        }
    }
}

template<int IN_W>
__device__ __forceinline__ void mma_phaseB(
    const __nv_bfloat16* Xh, const __nv_bfloat16* Wsm,
    int mt, int nh,
    wmma::fragment<wmma::accumulator,16,16,16,float>* Q)
{
    #pragma unroll 1
    for (int tap = 0; tap < 9; ++tap) {
        int toff = (tap / 3) * IN_W + (tap - (tap / 3) * 3);
        const __nv_bfloat16* A0 = Xh + (mt * 16 + toff) * 72;
        const __nv_bfloat16* B = Wsm + (tap * 64) * 72 + nh * 32;
        #pragma unroll
        for (int k = 0; k < 4; ++k) {
            wmma::fragment<wmma::matrix_a, 16, 16, 16, __nv_bfloat16, wmma::row_major> ah;
            wmma::load_matrix_sync(ah, A0 + k * 16, 72);
            #pragma unroll
            for (int nt = 0; nt < 2; ++nt) {
                wmma::fragment<wmma::matrix_b, 16, 16, 16, __nv_bfloat16, wmma::row_major> bl;
                wmma::load_matrix_sync(bl, B + k * 16 * 72 + nt * 16, 72);
                wmma::mma_sync(Q[nt], ah, bl, Q[nt]);
            }
        }
    }
}

__device__ __forceinline__ void load_w_smem(__nv_bfloat16* Wsm, const __nv_bfloat16* src, int tid) {
    const uint4* s = (const uint4*)src;
    for (int i = tid; i < 9 * 512; i += 832) {
        int e = i * 8;
        int ti = e >> 12, idx = e & 4095;
        int ic = idx >> 6, c8 = idx & 63;
        *(uint4*)&Wsm[(ti * 64 + ic) * 72 + c8] = s[i];
    }
}

__global__ __launch_bounds__(832, 1) void megaconv_kernel(
    const float* __restrict__ cb2, const float* __restrict__ g2,
    const float* __restrict__ bb2, const float* __restrict__ m2, const float* __restrict__ v2,
    const float* __restrict__ cb3, const float* __restrict__ g3,
    const float* __restrict__ bb3, const float* __restrict__ m3, const float* __restrict__ v3,
    const float* __restrict__ w4, const float* __restrict__ cb4,
    float* __restrict__ out)
{
    extern __shared__ char smc[];
    __nv_bfloat16* X2h = (__nv_bfloat16*)(smc + OX2H);
    __nv_bfloat16* X2l = (__nv_bfloat16*)(smc + OX2L);
    __nv_bfloat16* X3h = (__nv_bfloat16*)(smc + OX3H);
    __nv_bfloat16* X3l = (__nv_bfloat16*)(smc + OX3L);
    __nv_bfloat16* Wsm = (__nv_bfloat16*)(smc + OWB);
    float* sbs = (float*)(smc + OSBS);    // [0,128) conv2, [128,256) conv3
    __shared__ float ws4[576];
    __shared__ float red[32];

    const int b = blockIdx.x, tid = threadIdx.x, wid = tid >> 5, lane = tid & 31;

    // ---- prologue: X2 from gmem, W2 hi, sbs2, sbs3 ----
    {
        const uint4* sh = (const uint4*)(g_x1h + (size_t)b * 225 * 64);
        const uint4* sl = (const uint4*)(g_x1l + (size_t)b * 225 * 64);
        for (int i = tid; i < 225 * 8; i += 832) {
            int p = i >> 3, c8 = (i & 7) * 8;
            *(uint4*)&X2h[p * 72 + c8] = sh[i];
            *(uint4*)&X2l[p * 72 + c8] = sl[i];
        }
        uint4 z = make_uint4(0, 0, 0, 0);
        for (int i = tid; i < 15 * 8; i += 832) {
            int p = 225 + (i >> 3), c8 = (i & 7) * 8;
            *(uint4*)&X2h[p * 72 + c8] = z;
            *(uint4*)&X2l[p * 72 + c8] = z;
        }
        for (int i = tid; i < 7 * 8; i += 832) {
            int p = 169 + (i >> 3), c8 = (i & 7) * 8;
            *(uint4*)&X3h[p * 72 + c8] = z;
            *(uint4*)&X3l[p * 72 + c8] = z;
        }
    }
    if (tid < 64) {
        float s = g2[tid] * rsqrtf(v2[tid] + 1e-5f);
        sbs[tid] = s;
        sbs[64 + tid] = s * (cb2[tid] - m2[tid]) + bb2[tid];
    } else if (tid >= 64 && tid < 128) {
        int t = tid - 64;
        float s = g3[t] * rsqrtf(v3[t] + 1e-5f);
        sbs[128 + t] = s;
        sbs[192 + t] = s * (cb3[t] - m3[t]) + bb3[t];
    }
    load_w_smem(Wsm, g_wh, tid);
    __syncthreads();

    // ======== conv2: 26 warp units (13 mt x 2 nh) ========
    {
        const int mt = wid >> 1, nh = wid & 1;
        wmma::fragment<wmma::accumulator, 16, 16, 16, float> P[2], Q[2];
        wmma::fill_fragment(P[0], 0.f); wmma::fill_fragment(P[1], 0.f);
        wmma::fill_fragment(Q[0], 0.f); wmma::fill_fragment(Q[1], 0.f);

        mma_phaseA<15>(X2h, X2l, Wsm, mt, nh, P, Q);
        __syncthreads();
        load_w_smem(Wsm, g_wl, tid);
        __syncthreads();
        mma_phaseB<15>(X2h, Wsm, mt, nh, Q);

        #pragma unroll
        for (int nt = 0; nt < 2; ++nt)
            #pragma unroll
            for (int i = 0; i < P[nt].num_elements; ++i)
                P[nt].x[i] += Q[nt].x[i];

        __syncthreads();   // X2 & W reads complete
        float* patch = (float*)(smc) + wid * 16 * 36;
        wmma::store_matrix_sync(patch,      P[0], 36, wmma::mem_row_major);
        wmma::store_matrix_sync(patch + 16, P[1], 36, wmma::mem_row_major);
        __syncwarp();
        int r = lane & 15, ch = (lane >> 4) * 16;
        int p = mt * 16 + r;
        int y = p / 15, x = p - y * 15;
        if (y < 13 && x < 13) {
            int orow = y * 13 + x;
            int c0 = nh * 32 + ch;
            unsigned uh[8], ul[8];
            #pragma unroll
            for (int q = 0; q < 8; ++q) {
                int c = c0 + 2 * q;
                float v0 = fmaxf(sbs[c] * patch[r * 36 + ch + 2*q] + sbs[64 + c], 0.f);
                float v1_ = fmaxf(sbs[c+1] * patch[r * 36 + ch + 2*q + 1] + sbs[64 + c + 1], 0.f);
                __nv_bfloat16 h0 = __float2bfloat16(v0), h1 = __float2bfloat16(v1_);
                uh[q] = (unsigned)__bfloat16_as_ushort(h0) | ((unsigned)__bfloat16_as_ushort(h1) << 16);
                ul[q] = pack2bf(v0 - __bfloat162float(h0), v1_ - __bfloat162float(h1));
            }
            uint4* dh = (uint4*)&X3h[orow * 72 + c0];
            uint4* dl = (uint4*)&X3l[orow * 72 + c0];
            dh[0] = make_uint4(uh[0], uh[1], uh[2], uh[3]);
            dh[1] = make_uint4(uh[4], uh[5], uh[6], uh[7]);
            dl[0] = make_uint4(ul[0], ul[1], ul[2], ul[3]);
            dl[1] = make_uint4(ul[4], ul[5], ul[6], ul[7]);
        }
    }
    __syncthreads();

    // ======== conv3: 18 warp units (9 mt x 2 nh), warps 0..17 ========
    load_w_smem(Wsm, g_wh + 36864, tid);
    __syncthreads();
    {
        const bool act = wid < 18;
        const int mt = wid >> 1, nh = wid & 1;
        wmma::fragment<wmma::accumulator, 16, 16, 16, float> P[2], Q[2];
        wmma::fill_fragment(P[0], 0.f); wmma::fill_fragment(P[1], 0.f);
        wmma::fill_fragment(Q[0], 0.f); wmma::fill_fragment(Q[1], 0.f);

        if (act) mma_phaseA<13>(X3h, X3l, Wsm, mt, nh, P, Q);
        __syncthreads();
        load_w_smem(Wsm, g_wl + 36864, tid);
        __syncthreads();
        if (act) mma_phaseB<13>(X3h, Wsm, mt, nh, Q);

        #pragma unroll
        for (int nt = 0; nt < 2; ++nt)
            #pragma unroll
            for (int i = 0; i < P[nt].num_elements; ++i)
                P[nt].x[i] += Q[nt].x[i];

        __syncthreads();   // X3 & W reads complete
        float* x3s = (float*)(smc + 41472);
        for (int i = tid; i < 576; i += 832) ws4[i] = w4[i];
        if (act) {
            float* patch = (float*)(smc) + wid * 16 * 36;
            wmma::store_matrix_sync(patch,      P[0], 36, wmma::mem_row_major);
            wmma::store_matrix_sync(patch + 16, P[1], 36, wmma::mem_row_major);
            __syncwarp();
            int r = lane & 15, ch = (lane >> 4) * 16;
            int p = mt * 16 + r;
            int y = p / 13, x = p - y * 13;
            if (y < 11 && x < 11) {
                int orow = y * 11 + x;
                #pragma unroll
                for (int j = 0; j < 16; ++j) {
                    int c = nh * 32 + ch + j;
                    x3s[orow * 68 + c] = fmaxf(sbs[128 + c] * patch[r * 36 + ch + j] + sbs[192 + c], 0.f);
                }
            }
        }
    }
    __syncthreads();

    // ======== conv4 (64->1, 11x11 -> 9x9) + global max ========
    {
        const float* x3s = (const float*)(smc + 41472);
        float lm = -INFINITY;
        if (tid < 81) {
            int y = tid / 9, x = tid - (tid / 9) * 9;
            float a = 0.f;
            #pragma unroll
            for (int ky = 0; ky < 3; ++ky)
                #pragma unroll
                for (int kx = 0; kx < 3; ++kx) {
                    const float* row = x3s + ((y + ky) * 11 + (x + kx)) * 68;
                    int t = ky * 3 + kx;
                    for (int ic = 0; ic < 64; ++ic)
                        a += row[ic] * ws4[ic * 9 + t];
                }
            lm = a;
        }
        #pragma unroll
        for (int off = 16; off > 0; off >>= 1) lm = fmaxf(lm, __shfl_xor_sync(0xffffffffu, lm, off));
        if (lane == 0) red[wid] = lm;
        __syncthreads();
        if (tid == 0) {
            float v = -INFINITY;
            #pragma unroll
            for (int i = 0; i < 26; ++i) v = fmaxf(v, red[i]);
            out[b] = v + cb4[0];
        }
    }
}

// ---------------------------------------------------------------------------
extern "C" void kernel_launch(void* const* d_in, const int* in_sizes, int n_in,
                              void* d_out, int out_size)
{
    static bool init = false;
    if (!init) {
        cudaFuncSetAttribute(megaconv_kernel, cudaFuncAttributeMaxDynamicSharedMemorySize, SMEGA);
        init = true;
    }

    wprep_kernel<<<288, 256>>>((const float*)d_in[11], (const float*)d_in[17]);

    stats_conv1_kernel<<<BTOT, 1024>>>(
        (const float*)d_in[0], (const float*)d_in[1],
        (const float*)d_in[2], (const float*)d_in[3], d_in[4],
        (const float*)d_in[5],  (const float*)d_in[6],
        (const float*)d_in[7],  (const float*)d_in[8],
        (const float*)d_in[9],  (const float*)d_in[10]);

    megaconv_kernel<<<BTOT, 832, SMEGA>>>(
        (const float*)d_in[12], (const float*)d_in[13],
        (const float*)d_in[14], (const float*)d_in[15], (const float*)d_in[16],
        (const float*)d_in[18], (const float*)d_in[19],
        (const float*)d_in[20], (const float*)d_in[21], (const float*)d_in[22],
        (const float*)d_in[23], (const float*)d_in[24],
        (float*)d_out);
}

// round 16
// speedup vs baseline: 1.4982x; 1.4982x over previous
#include <cuda_runtime.h>
#include <cuda_bf16.h>
#include <mma.h>
#include <math.h>
#include <stdint.h>

using namespace nvcuda;

#define BTOT 512
#define NMEM 30
#define HW 1024
#define NGTH_ 15

typedef unsigned long long u64;

__device__ __forceinline__ u64 dup2f(float v){u64 r;asm("mov.b64 %0,{%1,%1};":"=l"(r):"f"(v));return r;}
__device__ __forceinline__ void fma2(u64&d,u64 a,u64 b){asm("fma.rn.f32x2 %0,%1,%2,%0;":"+l"(d):"l"(a),"l"(b));}
__device__ __forceinline__ float2 unp2(u64 v){float lo,hi;asm("mov.b64 {%0,%1},%2;":"=f"(lo),"=f"(hi):"l"(v));return make_float2(lo,hi);}

__device__ float g_inp6[(size_t)BTOT*6*HW];
__device__ float g_cst[(size_t)BTOT*8];
__device__ __nv_bfloat16 g_x1h[(size_t)BTOT*225*64];
__device__ __nv_bfloat16 g_x1l[(size_t)BTOT*225*64];
__device__ __nv_bfloat16 g_x2h[(size_t)BTOT*169*64];
__device__ __nv_bfloat16 g_x2l[(size_t)BTOT*169*64];
__device__ __nv_bfloat16 g_wh[2*9*4096];      // [conv][tap][ic][oc] hi
__device__ __nv_bfloat16 g_wl[2*9*4096];      // lo

__device__ __forceinline__ unsigned pack2bf(float a, float b) {
    return (unsigned)__bfloat16_as_ushort(__float2bfloat16(a)) |
           ((unsigned)__bfloat16_as_ushort(__float2bfloat16(b)) << 16);
}

// ---------------------------------------------------------------------------
// Kernel 0: weight prep — w2/w3 -> bf16 hi/lo, tap-major coalesced layout
// ---------------------------------------------------------------------------
__global__ __launch_bounds__(256) void wprep_kernel(
    const float* __restrict__ w2, const float* __restrict__ w3)
{
    int i = blockIdx.x * 256 + threadIdx.x;
    if (i < 2 * 9 * 4096) {
        int conv = i / 36864, r = i - conv * 36864;
        int tap = r >> 12, idx = r & 4095;
        int ic = idx >> 6, oc = idx & 63;
        const float* w = conv ? w3 : w2;
        float v = w[oc * 576 + ic * 9 + tap];
        __nv_bfloat16 h = __float2bfloat16(v);
        g_wh[i] = h;
        g_wl[i] = __float2bfloat16(v - __bfloat162float(h));
    }
}

// ---------------------------------------------------------------------------
// Kernel 1: stats — 1024 threads (1/pixel), high-MLP  (validated R11/R13)
// ---------------------------------------------------------------------------
__global__ __launch_bounds__(1024) void stats_kernel(
    const float* __restrict__ ts, const float* __restrict__ ptm,
    const float* __restrict__ pmt, const float* __restrict__ piou,
    const void* __restrict__ mask_raw)
{
    const int b = blockIdx.x, tid = threadIdx.x, lane = tid & 31, wid = tid >> 5;
    __shared__ float mf[NMEM], ow[NMEM], pmax[NMEM], warpmax[32], sc[16];

    unsigned int w0 = *(const unsigned int*)mask_raw;
    int mode = (w0 == 1u) ? 1 : ((w0 == 0x3F800000u) ? 2 : 0);

    if (tid == 0) {
        float run = 0.f, ca = 0.f, cg = 0.f, co = 0.f;
        for (int m = 0; m < NMEM; ++m) {
            int idx = b * NMEM + m; float f;
            if (mode == 1)      f = (((const int*)mask_raw)[idx] != 0) ? 1.f : 0.f;
            else if (mode == 2) f = (((const float*)mask_raw)[idx] != 0.f) ? 1.f : 0.f;
            else                f = (((const unsigned char*)mask_raw)[idx] != 0) ? 1.f : 0.f;
            run += f;
            float g = (run - 1.f < (float)NGTH_) ? f : 0.f;
            float o = f - g;
            mf[m] = f; ow[m] = o; ca += f; cg += g; co += o;
        }
        sc[7] = ca; sc[8] = cg; sc[9] = co;
    }

    {
        float v = ts[(size_t)b * HW + tid];
        #pragma unroll
        for (int off = 16; off > 0; off >>= 1) v = fmaxf(v, __shfl_xor_sync(0xffffffffu, v, off));
        if (lane == 0) warpmax[wid] = v;
    }

    if (wid < NMEM) {
        const float* pr = ptm + (size_t)b * NMEM * HW + (size_t)wid * HW;
        float mx = -INFINITY;
        #pragma unroll
        for (int k = 0; k < 32; ++k) mx = fmaxf(mx, pr[lane + 32 * k]);
        #pragma unroll
        for (int off = 16; off > 0; off >>= 1) mx = fmaxf(mx, __shfl_xor_sync(0xffffffffu, mx, off));
        if (lane == 0) pmax[wid] = mx;
    }
    __syncthreads();

    if (wid == 0) {
        float v = warpmax[lane];
        #pragma unroll
        for (int off = 16; off > 0; off >>= 1) v = fmaxf(v, __shfl_xor_sync(0xffffffffu, v, off));
        if (lane == 0) sc[0] = v;
    }
    if (wid == 1) {
        float v  = (lane < NMEM) ? pmax[lane] : 0.f;
        float fa = (lane < NMEM) ? mf[lane] : 0.f;
        float fo = (lane < NMEM) ? ow[lane] : 0.f;
        float fg = fa - fo;
        float sa = v*fa, ssa = v*v*fa, sg = v*fg, ssg = v*v*fg, so = v*fo, sso = v*v*fo;
        #pragma unroll
        for (int off = 16; off > 0; off >>= 1) {
            sa  += __shfl_xor_sync(0xffffffffu, sa, off);  ssa += __shfl_xor_sync(0xffffffffu, ssa, off);
            sg  += __shfl_xor_sync(0xffffffffu, sg, off);  ssg += __shfl_xor_sync(0xffffffffu, ssg, off);
            so  += __shfl_xor_sync(0xffffffffu, so, off);  sso += __shfl_xor_sync(0xffffffffu, sso, off);
        }
        if (lane == 0) {
            float ca = sc[7], cg = sc[8], co = sc[9];
            float mA = sa / ca; sc[1] = mA; sc[2] = sqrtf(fmaxf(ssa / ca - mA * mA, 0.f));
            float mG = sg / cg; sc[3] = mG; sc[4] = sqrtf(fmaxf(ssg / cg - mG * mG, 0.f));
            float mO = so / co; sc[5] = mO; sc[6] = sqrtf(fmaxf(sso / co - mO * mO, 0.f));
        }
    }
    __syncthreads();

    if (tid == 0) {
        float* c = g_cst + (size_t)b * 8;
        c[0] = sc[0]; c[1] = piou[b]; c[2] = sc[1]; c[3] = sc[2];
        c[4] = sc[3]; c[5] = sc[4];   c[6] = sc[5]; c[7] = sc[6];
    }

    {
        const float* pmtb = pmt + (size_t)b * NMEM * HW + tid;
        const float ca = sc[7], co = sc[9];
        float sa = 0, ssa = 0, sg = 0, ssg = 0, so = 0, sso = 0;
        #pragma unroll
        for (int m = 0; m < NMEM; ++m) {
            float v = pmtb[(size_t)m * HW];
            float fa = mf[m], fo = ow[m];
            sa += v * fa; ssa += v * v * fa;
            if (m < NGTH_) { sg += v; ssg += v * v; }
            so += v * fo; sso += v * v * fo;
        }
        float mA = sa / ca, sA = sqrtf(fmaxf(ssa / ca - mA * mA, 0.f));
        float mG = sg * (1.f / NGTH_), sG = sqrtf(fmaxf(ssg * (1.f / NGTH_) - mG * mG, 0.f));
        float mO = so / co, sO = sqrtf(fmaxf(sso / co - mO * mO, 0.f));
        float* ob = g_inp6 + (size_t)b * 6 * HW + tid;
        ob[0*HW] = mA; ob[1*HW] = sA; ob[2*HW] = mG;
        ob[3*HW] = sG; ob[4*HW] = mO; ob[5*HW] = sO;
    }
}

// ---------------------------------------------------------------------------
// Kernel 2: conv1 + bn + relu + pool -> g_x1h/l (bf16 split)  (validated R13)
// ---------------------------------------------------------------------------
#define TPB1 480
__global__ __launch_bounds__(TPB1, 1) void conv1_kernel(
    const float* __restrict__ w1, const float* __restrict__ cb1,
    const float* __restrict__ g1, const float* __restrict__ bb1,
    const float* __restrict__ m1, const float* __restrict__ v1)
{
    __shared__ float sm[6528 + 3456 + 128];
    const int IW_ = 6528, IE_ = 9984;
    const int b = blockIdx.x, tid = threadIdx.x;

    {
        const float* src = g_inp6 + (size_t)b * 6 * HW;
        for (int i = tid; i < 6 * HW; i += TPB1) {
            int c = i >> 10; int rem = i & 1023;
            sm[c * 1088 + (rem >> 5) * 34 + (rem & 31)] = src[i];
        }
        for (int i = tid; i < 64 * 6 * 9; i += TPB1) {
            int oc = i / 54; int r = i - oc * 54;
            int c = r / 9; int t = r - c * 9;
            sm[IW_ + ((oc >> 1) * 6 + c) * 18 + t * 2 + (oc & 1)] = w1[oc * 126 + (c + 2) * 9 + t];
        }
        if (tid < 64) {
            const float* cst = g_cst + (size_t)b * 8;
            float extra = 0.f;
            #pragma unroll
            for (int j = 0; j < 8; ++j) {
                int ic = (j < 2) ? j : (j + 6);
                const float* wb = w1 + tid * 126 + ic * 9;
                float s9 = 0.f;
                #pragma unroll
                for (int t = 0; t < 9; ++t) s9 += wb[t];
                extra += cst[j] * s9;
            }
            float s = g1[tid] * rsqrtf(v1[tid] + 1e-5f);
            sm[IE_ + tid] = s;
            sm[IE_ + 64 + tid] = s * (extra + cb1[tid] - m1[tid]) + bb1[tid];
        }
    }
    __syncthreads();

    __nv_bfloat16* xoh = g_x1h + (size_t)b * 225 * 64;
    __nv_bfloat16* xol = g_x1l + (size_t)b * 225 * 64;
    #pragma unroll
    for (int itb = 0; itb < 2; ++itb) {
        int it = tid + itb * TPB1;
        int ocg = it / 60;
        int r = it - ocg * 60;
        int pr = r >> 2, pq = r & 3;
        int x0 = 8 * pq, r0 = 2 * pr;

        u64 acc[2][2][8];
        #pragma unroll
        for (int p = 0; p < 2; ++p)
            #pragma unroll
            for (int e = 0; e < 2; ++e)
                #pragma unroll
                for (int c = 0; c < 8; ++c) acc[p][e][c] = 0ull;

        for (int ch = 0; ch < 6; ++ch) {
            const float* ib = &sm[ch * 1088 + r0 * 34 + x0];
            const u64* wb0 = (const u64*)&sm[IW_ + ((ocg * 2) * 6 + ch) * 18];
            const u64* wb1 = (const u64*)&sm[IW_ + ((ocg * 2 + 1) * 6 + ch) * 18];
            #pragma unroll
            for (int ir = 0; ir < 4; ++ir) {
                u64 d[10];
                #pragma unroll
                for (int q = 0; q < 5; ++q) {
                    float2 a = *(const float2*)(ib + ir * 34 + 2 * q);
                    d[2*q] = dup2f(a.x); d[2*q+1] = dup2f(a.y);
                }
                #pragma unroll
                for (int kx = 0; kx < 3; ++kx) {
                    if (ir <= 2) {
                        u64 wa = wb0[ir*3+kx], wc = wb1[ir*3+kx];
                        #pragma unroll
                        for (int c = 0; c < 8; ++c) { fma2(acc[0][0][c], wa, d[c+kx]); fma2(acc[1][0][c], wc, d[c+kx]); }
                    }
                    if (ir >= 1) {
                        u64 wa = wb0[(ir-1)*3+kx], wc = wb1[(ir-1)*3+kx];
                        #pragma unroll
                        for (int c = 0; c < 8; ++c) { fma2(acc[0][1][c], wa, d[c+kx]); fma2(acc[1][1][c], wc, d[c+kx]); }
                    }
                }
            }
        }
        #pragma unroll
        for (int p = 0; p < 2; ++p) {
            int oc0 = ocg * 4 + 2 * p;
            float s0 = sm[IE_+oc0], bi0 = sm[IE_+64+oc0];
            float s1 = sm[IE_+oc0+1], bi1 = sm[IE_+64+oc0+1];
            #pragma unroll
            for (int j = 0; j < 4; ++j) {
                int pt = 4 * pq + j;
                if (pt < 15) {
                    float2 a = unp2(acc[p][0][2*j]), bq = unp2(acc[p][0][2*j+1]);
                    float2 cq = unp2(acc[p][1][2*j]), e = unp2(acc[p][1][2*j+1]);
                    float v0 = fmaxf(fmaxf(fmaxf(s0*a.x+bi0,0.f), fmaxf(s0*bq.x+bi0,0.f)),
                                     fmaxf(fmaxf(s0*cq.x+bi0,0.f), fmaxf(s0*e.x+bi0,0.f)));
                    float v1_ = fmaxf(fmaxf(fmaxf(s1*a.y+bi1,0.f), fmaxf(s1*bq.y+bi1,0.f)),
                                      fmaxf(fmaxf(s1*cq.y+bi1,0.f), fmaxf(s1*e.y+bi1,0.f)));
                    int pos = pr * 15 + pt;
                    __nv_bfloat16 h0 = __float2bfloat16(v0), h1 = __float2bfloat16(v1_);
                    *(unsigned*)&xoh[pos * 64 + oc0] =
                        (unsigned)__bfloat16_as_ushort(h0) | ((unsigned)__bfloat16_as_ushort(h1) << 16);
                    *(unsigned*)&xol[pos * 64 + oc0] =
                        pack2bf(v0 - __bfloat162float(h0), v1_ - __bfloat162float(h1));
                }
            }
        }
    }
}

// ---------------------------------------------------------------------------
// Kernel 3/4: conv 64->64, 9 tap-GEMMs, bf16 3-pass with MERGED phases:
// Wh fully resident (9 taps), Wl streamed in WLCH-tap chunks.
// Per (tap,k): load ah,al once; 3 MMAs against bh + bl.
// ---------------------------------------------------------------------------
template<int IN_W, int OUT_W, bool FUSE4, int TPB, int WLCH>
__global__ __launch_bounds__(TPB, 1) void convmma_kernel(
    const __nv_bfloat16* __restrict__ xinh, const __nv_bfloat16* __restrict__ xinl,
    __nv_bfloat16* __restrict__ xouth, __nv_bfloat16* __restrict__ xoutl,
    int woff,
    const float* __restrict__ cb,
    const float* __restrict__ gg, const float* __restrict__ bbv,
    const float* __restrict__ mmv, const float* __restrict__ vvv,
    const float* __restrict__ w4, const float* __restrict__ cb4,
    float* __restrict__ out)
{
    constexpr int INROWS = IN_W * IN_W;
    constexpr int MMAX = (OUT_W - 1) * IN_W + OUT_W;
    constexpr int MTILES = (MMAX + 15) / 16;
    constexpr int XROWS = ((MTILES * 16 + 2 * IN_W + 2 + 15) / 16) * 16;
    constexpr int LDX = 72, LDW = 72;
    constexpr int OXH = 0;
    constexpr int OXL = OXH + XROWS * LDX * 2;
    constexpr int OWH = OXL + XROWS * LDX * 2;
    constexpr int OWL = OWH + 9 * 64 * LDW * 2;          // Wh: 82944 B
    constexpr int OSB = OWL + WLCH * 64 * LDW * 2;       // Wl chunk buffer

    extern __shared__ char smc[];
    __nv_bfloat16* Xh = (__nv_bfloat16*)(smc + OXH);
    __nv_bfloat16* Xl = (__nv_bfloat16*)(smc + OXL);
    __nv_bfloat16* Wh = (__nv_bfloat16*)(smc + OWH);
    __nv_bfloat16* Wl = (__nv_bfloat16*)(smc + OWL);
    float* sbs = (float*)(smc + OSB);
    __shared__ float ws4[576];
    __shared__ float red[32];

    const int b = blockIdx.x, tid = threadIdx.x, wid = tid >> 5, lane = tid & 31;

    // X hi/lo into smem — vectorized (8 bf16 per uint4)
    {
        const uint4* sh = (const uint4*)(xinh + (size_t)b * INROWS * 64);
        const uint4* sl = (const uint4*)(xinl + (size_t)b * INROWS * 64);
        for (int i = tid; i < INROWS * 8; i += TPB) {
            int p = i >> 3, c8 = (i & 7) * 8;
            *(uint4*)&Xh[p * LDX + c8] = sh[i];
            *(uint4*)&Xl[p * LDX + c8] = sl[i];
        }
        uint4 z = make_uint4(0, 0, 0, 0);
        for (int i = tid; i < (XROWS - INROWS) * 8; i += TPB) {
            int p = INROWS + (i >> 3), c8 = (i & 7) * 8;
            *(uint4*)&Xh[p * LDX + c8] = z;
            *(uint4*)&Xl[p * LDX + c8] = z;
        }
    }
    if (tid < 64) {
        float s = gg[tid] * rsqrtf(vvv[tid] + 1e-5f);
        sbs[tid] = s;
        sbs[64 + tid] = s * (cb[tid] - mmv[tid]) + bbv[tid];
    }
    // Wh (all 9 taps) — vectorized
    {
        const uint4* sh = (const uint4*)(g_wh + woff);
        for (int i = tid; i < 9 * 512; i += TPB) {
            int e = i * 8;
            int ti = e >> 12, idx = e & 4095;
            int ic = idx >> 6, c8 = idx & 63;
            *(uint4*)&Wh[(ti * 64 + ic) * LDW + c8] = sh[i];
        }
    }

    const int mt = wid >> 1, nh = wid & 1;
    constexpr int NUNITS = MTILES * 2;
    const bool act = wid < NUNITS;

    wmma::fragment<wmma::accumulator, 16, 16, 16, float> P[2], Q[2];
    wmma::fill_fragment(P[0], 0.f); wmma::fill_fragment(P[1], 0.f);
    wmma::fill_fragment(Q[0], 0.f); wmma::fill_fragment(Q[1], 0.f);

    for (int c0 = 0; c0 < 9; c0 += WLCH) {
        const int ntaps = (9 - c0 < WLCH) ? (9 - c0) : WLCH;
        __syncthreads();     // Wl buffer free (prev chunk consumed) / first: orders X+Wh
        {
            const uint4* sl = (const uint4*)(g_wl + woff + c0 * 4096);
            for (int i = tid; i < ntaps * 512; i += TPB) {
                int e = i * 8;
                int ti = e >> 12, idx = e & 4095;
                int ic = idx >> 6, c8 = idx & 63;
                *(uint4*)&Wl[(ti * 64 + ic) * LDW + c8] = sl[i];
            }
        }
        __syncthreads();

        if (act) {
            #pragma unroll 1
            for (int tt = 0; tt < ntaps; ++tt) {
                int tap = c0 + tt;
                int toff = (tap / 3) * IN_W + (tap - (tap / 3) * 3);
                const __nv_bfloat16* A0 = Xh + (mt * 16 + toff) * LDX;
                const __nv_bfloat16* A1 = Xl + (mt * 16 + toff) * LDX;
                const __nv_bfloat16* Bh = Wh + (tap * 64) * LDW + nh * 32;
                const __nv_bfloat16* Bl = Wl + (tt * 64) * LDW + nh * 32;
                #pragma unroll
                for (int k = 0; k < 4; ++k) {
                    wmma::fragment<wmma::matrix_a, 16, 16, 16, __nv_bfloat16, wmma::row_major> ah, al;
                    wmma::load_matrix_sync(ah, A0 + k * 16, LDX);
                    wmma::load_matrix_sync(al, A1 + k * 16, LDX);
                    #pragma unroll
                    for (int nt = 0; nt < 2; ++nt) {
                        wmma::fragment<wmma::matrix_b, 16, 16, 16, __nv_bfloat16, wmma::row_major> bh, bl;
                        wmma::load_matrix_sync(bh, Bh + k * 16 * LDW + nt * 16, LDW);
                        wmma::load_matrix_sync(bl, Bl + k * 16 * LDW + nt * 16, LDW);
                        wmma::mma_sync(P[nt], ah, bh, P[nt]);
                        wmma::mma_sync(Q[nt], al, bh, Q[nt]);
                        wmma::mma_sync(Q[nt], ah, bl, Q[nt]);
                    }
                }
            }
        }
    }

    #pragma unroll
    for (int nt = 0; nt < 2; ++nt)
        #pragma unroll
        for (int i = 0; i < P[nt].num_elements; ++i)
            P[nt].x[i] += Q[nt].x[i];

    // ---- epilogue: patch @0 (over X, dead); x3s @OWH (over Wh, dead) ----
    __syncthreads();
    float* patch = (float*)(smc) + wid * 16 * 36;
    float* x3s = (float*)(smc + OWH);
    if (FUSE4)
        for (int i = tid; i < 576; i += TPB) ws4[i] = w4[i];

    if (act) {
        wmma::store_matrix_sync(patch,      P[0], 36, wmma::mem_row_major);
        wmma::store_matrix_sync(patch + 16, P[1], 36, wmma::mem_row_major);
        __syncwarp();
        int r = lane & 15, ch = (lane >> 4) * 16;
        int p = mt * 16 + r;
        int y = p / IN_W, x = p - y * IN_W;
        if (y < OUT_W && x < OUT_W) {
            int orow = y * OUT_W + x;
            if (FUSE4) {
                #pragma unroll
                for (int j = 0; j < 16; ++j) {
                    int c = nh * 32 + ch + j;
                    x3s[orow * 68 + c] = fmaxf(sbs[c] * patch[r * 36 + ch + j] + sbs[64 + c], 0.f);
                }
            } else {
                int c0 = nh * 32 + ch;
                unsigned uh[8], ul[8];
                #pragma unroll
                for (int q = 0; q < 8; ++q) {
                    int c = c0 + 2 * q;
                    float v0 = fmaxf(sbs[c] * patch[r * 36 + ch + 2*q] + sbs[64 + c], 0.f);
                    float v1_ = fmaxf(sbs[c+1] * patch[r * 36 + ch + 2*q + 1] + sbs[64 + c + 1], 0.f);
                    __nv_bfloat16 h0 = __float2bfloat16(v0), h1 = __float2bfloat16(v1_);
                    uh[q] = (unsigned)__bfloat16_as_ushort(h0) | ((unsigned)__bfloat16_as_ushort(h1) << 16);
                    ul[q] = pack2bf(v0 - __bfloat162float(h0), v1_ - __bfloat162float(h1));
                }
                uint4* dh = (uint4*)&xouth[(size_t)b * OUT_W * OUT_W * 64 + orow * 64 + c0];
                uint4* dl = (uint4*)&xoutl[(size_t)b * OUT_W * OUT_W * 64 + orow * 64 + c0];
                dh[0] = make_uint4(uh[0], uh[1], uh[2], uh[3]);
                dh[1] = make_uint4(uh[4], uh[5], uh[6], uh[7]);
                dl[0] = make_uint4(ul[0], ul[1], ul[2], ul[3]);
                dl[1] = make_uint4(ul[4], ul[5], ul[6], ul[7]);
            }
        }
        __syncwarp();
    }

    if (FUSE4) {
        __syncthreads();
        float lm = -INFINITY;
        if (tid < 81) {
            int y = tid / 9, x = tid - (tid / 9) * 9;
            float a = 0.f;
            #pragma unroll
            for (int ky = 0; ky < 3; ++ky)
                #pragma unroll
                for (int kx = 0; kx < 3; ++kx) {
                    const float* row = x3s + ((y + ky) * OUT_W + (x + kx)) * 68;
                    int t = ky * 3 + kx;
                    for (int ic = 0; ic < 64; ++ic)
                        a += row[ic] * ws4[ic * 9 + t];
                }
            lm = a;
        }
        #pragma unroll
        for (int off = 16; off > 0; off >>= 1) lm = fmaxf(lm, __shfl_xor_sync(0xffffffffu, lm, off));
        if (lane == 0) red[wid] = lm;
        __syncthreads();
        if (tid == 0) {
            float v = -INFINITY;
            for (int i = 0; i < TPB / 32; ++i) v = fmaxf(v, red[i]);
            out[b] = v + cb4[0];
        }
    }
}

// ---------------------------------------------------------------------------
extern "C" void kernel_launch(void* const* d_in, const int* in_sizes, int n_in,
                              void* d_out, int out_size)
{
    // conv2: X 69120 + Wh 82944 + Wl(5 taps) 46080 + sbs 512 = 198656
    // conv3: X 50688 + Wh 82944 + Wl(9 taps) 82944 + sbs 512 = 217088
    const int S2 = 198656;
    const int S3 = 217088;
    static __nv_bfloat16 *x1h = nullptr, *x1l = nullptr, *x2h = nullptr, *x2l = nullptr;
    if (!x1h) {
        cudaGetSymbolAddress((void**)&x1h, g_x1h);
        cudaGetSymbolAddress((void**)&x1l, g_x1l);
        cudaGetSymbolAddress((void**)&x2h, g_x2h);
        cudaGetSymbolAddress((void**)&x2l, g_x2l);
        cudaFuncSetAttribute(convmma_kernel<15,13,false,832,5>, cudaFuncAttributeMaxDynamicSharedMemorySize, S2);
        cudaFuncSetAttribute(convmma_kernel<13,11,true,576,9>,  cudaFuncAttributeMaxDynamicSharedMemorySize, S3);
    }

    wprep_kernel<<<288, 256>>>((const float*)d_in[11], (const float*)d_in[17]);

    stats_kernel<<<BTOT, 1024>>>(
        (const float*)d_in[0], (const float*)d_in[1],
        (const float*)d_in[2], (const float*)d_in[3], d_in[4]);

    conv1_kernel<<<BTOT, TPB1>>>(
        (const float*)d_in[5],  (const float*)d_in[6],
        (const float*)d_in[7],  (const float*)d_in[8],
        (const float*)d_in[9],  (const float*)d_in[10]);

    convmma_kernel<15,13,false,832,5><<<BTOT, 832, S2>>>(
        x1h, x1l, x2h, x2l, 0,
        (const float*)d_in[12],
        (const float*)d_in[13], (const float*)d_in[14],
        (const float*)d_in[15], (const float*)d_in[16],
        nullptr, nullptr, nullptr);

    convmma_kernel<13,11,true,576,9><<<BTOT, 576, S3>>>(
        x2h, x2l, nullptr, nullptr, 36864,
        (const float*)d_in[18],
        (const float*)d_in[19], (const float*)d_in[20],
        (const float*)d_in[21], (const float*)d_in[22],
        (const float*)d_in[23], (const float*)d_in[24],
        (float*)d_out);
}

// round 17
// speedup vs baseline: 1.6380x; 1.0934x over previous
#include <cuda_runtime.h>
#include <cuda_bf16.h>
#include <mma.h>
#include <math.h>
#include <stdint.h>

using namespace nvcuda;

#define BTOT 512
#define NMEM 30
#define HW 1024
#define NGTH_ 15

typedef unsigned long long u64;

__device__ __forceinline__ u64 dup2f(float v){u64 r;asm("mov.b64 %0,{%1,%1};":"=l"(r):"f"(v));return r;}
__device__ __forceinline__ void fma2(u64&d,u64 a,u64 b){asm("fma.rn.f32x2 %0,%1,%2,%0;":"+l"(d):"l"(a),"l"(b));}
__device__ __forceinline__ float2 unp2(u64 v){float lo,hi;asm("mov.b64 {%0,%1},%2;":"=f"(lo),"=f"(hi):"l"(v));return make_float2(lo,hi);}

__device__ float g_inp6[(size_t)BTOT*6*HW];
__device__ float g_cst[(size_t)BTOT*8];
__device__ __nv_bfloat16 g_x1h[(size_t)BTOT*225*64];
__device__ __nv_bfloat16 g_x1l[(size_t)BTOT*225*64];
__device__ __nv_bfloat16 g_x2h[(size_t)BTOT*169*64];
__device__ __nv_bfloat16 g_x2l[(size_t)BTOT*169*64];
__device__ float g_x3[(size_t)BTOT*121*64];
__device__ __nv_bfloat16 g_wh[2*9*4096];      // [conv][tap][ic][oc] hi
__device__ __nv_bfloat16 g_wl[2*9*4096];      // lo

__device__ __forceinline__ unsigned pack2bf(float a, float b) {
    return (unsigned)__bfloat16_as_ushort(__float2bfloat16(a)) |
           ((unsigned)__bfloat16_as_ushort(__float2bfloat16(b)) << 16);
}

// ---------------------------------------------------------------------------
// Kernel 0: weight prep (validated)
// ---------------------------------------------------------------------------
__global__ __launch_bounds__(256) void wprep_kernel(
    const float* __restrict__ w2, const float* __restrict__ w3)
{
    int i = blockIdx.x * 256 + threadIdx.x;
    if (i < 2 * 9 * 4096) {
        int conv = i / 36864, r = i - conv * 36864;
        int tap = r >> 12, idx = r & 4095;
        int ic = idx >> 6, oc = idx & 63;
        const float* w = conv ? w3 : w2;
        float v = w[oc * 576 + ic * 9 + tap];
        __nv_bfloat16 h = __float2bfloat16(v);
        g_wh[i] = h;
        g_wl[i] = __float2bfloat16(v - __bfloat162float(h));
    }
}

// ---------------------------------------------------------------------------
// Kernel 1: stats — 1024 threads (validated R11/R13)
// ---------------------------------------------------------------------------
__global__ __launch_bounds__(1024) void stats_kernel(
    const float* __restrict__ ts, const float* __restrict__ ptm,
    const float* __restrict__ pmt, const float* __restrict__ piou,
    const void* __restrict__ mask_raw)
{
    const int b = blockIdx.x, tid = threadIdx.x, lane = tid & 31, wid = tid >> 5;
    __shared__ float mf[NMEM], ow[NMEM], pmax[NMEM], warpmax[32], sc[16];

    unsigned int w0 = *(const unsigned int*)mask_raw;
    int mode = (w0 == 1u) ? 1 : ((w0 == 0x3F800000u) ? 2 : 0);

    if (tid == 0) {
        float run = 0.f, ca = 0.f, cg = 0.f, co = 0.f;
        for (int m = 0; m < NMEM; ++m) {
            int idx = b * NMEM + m; float f;
            if (mode == 1)      f = (((const int*)mask_raw)[idx] != 0) ? 1.f : 0.f;
            else if (mode == 2) f = (((const float*)mask_raw)[idx] != 0.f) ? 1.f : 0.f;
            else                f = (((const unsigned char*)mask_raw)[idx] != 0) ? 1.f : 0.f;
            run += f;
            float g = (run - 1.f < (float)NGTH_) ? f : 0.f;
            float o = f - g;
            mf[m] = f; ow[m] = o; ca += f; cg += g; co += o;
        }
        sc[7] = ca; sc[8] = cg; sc[9] = co;
    }

    {
        float v = ts[(size_t)b * HW + tid];
        #pragma unroll
        for (int off = 16; off > 0; off >>= 1) v = fmaxf(v, __shfl_xor_sync(0xffffffffu, v, off));
        if (lane == 0) warpmax[wid] = v;
    }

    if (wid < NMEM) {
        const float* pr = ptm + (size_t)b * NMEM * HW + (size_t)wid * HW;
        float mx = -INFINITY;
        #pragma unroll
        for (int k = 0; k < 32; ++k) mx = fmaxf(mx, pr[lane + 32 * k]);
        #pragma unroll
        for (int off = 16; off > 0; off >>= 1) mx = fmaxf(mx, __shfl_xor_sync(0xffffffffu, mx, off));
        if (lane == 0) pmax[wid] = mx;
    }
    __syncthreads();

    if (wid == 0) {
        float v = warpmax[lane];
        #pragma unroll
        for (int off = 16; off > 0; off >>= 1) v = fmaxf(v, __shfl_xor_sync(0xffffffffu, v, off));
        if (lane == 0) sc[0] = v;
    }
    if (wid == 1) {
        float v  = (lane < NMEM) ? pmax[lane] : 0.f;
        float fa = (lane < NMEM) ? mf[lane] : 0.f;
        float fo = (lane < NMEM) ? ow[lane] : 0.f;
        float fg = fa - fo;
        float sa = v*fa, ssa = v*v*fa, sg = v*fg, ssg = v*v*fg, so = v*fo, sso = v*v*fo;
        #pragma unroll
        for (int off = 16; off > 0; off >>= 1) {
            sa  += __shfl_xor_sync(0xffffffffu, sa, off);  ssa += __shfl_xor_sync(0xffffffffu, ssa, off);
            sg  += __shfl_xor_sync(0xffffffffu, sg, off);  ssg += __shfl_xor_sync(0xffffffffu, ssg, off);
            so  += __shfl_xor_sync(0xffffffffu, so, off);  sso += __shfl_xor_sync(0xffffffffu, sso, off);
        }
        if (lane == 0) {
            float ca = sc[7], cg = sc[8], co = sc[9];
            float mA = sa / ca; sc[1] = mA; sc[2] = sqrtf(fmaxf(ssa / ca - mA * mA, 0.f));
            float mG = sg / cg; sc[3] = mG; sc[4] = sqrtf(fmaxf(ssg / cg - mG * mG, 0.f));
            float mO = so / co; sc[5] = mO; sc[6] = sqrtf(fmaxf(sso / co - mO * mO, 0.f));
        }
    }
    __syncthreads();

    if (tid == 0) {
        float* c = g_cst + (size_t)b * 8;
        c[0] = sc[0]; c[1] = piou[b]; c[2] = sc[1]; c[3] = sc[2];
        c[4] = sc[3]; c[5] = sc[4];   c[6] = sc[5]; c[7] = sc[6];
    }

    {
        const float* pmtb = pmt + (size_t)b * NMEM * HW + tid;
        const float ca = sc[7], co = sc[9];
        float sa = 0, ssa = 0, sg = 0, ssg = 0, so = 0, sso = 0;
        #pragma unroll
        for (int m = 0; m < NMEM; ++m) {
            float v = pmtb[(size_t)m * HW];
            float fa = mf[m], fo = ow[m];
            sa += v * fa; ssa += v * v * fa;
            if (m < NGTH_) { sg += v; ssg += v * v; }
            so += v * fo; sso += v * v * fo;
        }
        float mA = sa / ca, sA = sqrtf(fmaxf(ssa / ca - mA * mA, 0.f));
        float mG = sg * (1.f / NGTH_), sG = sqrtf(fmaxf(ssg * (1.f / NGTH_) - mG * mG, 0.f));
        float mO = so / co, sO = sqrtf(fmaxf(sso / co - mO * mO, 0.f));
        float* ob = g_inp6 + (size_t)b * 6 * HW + tid;
        ob[0*HW] = mA; ob[1*HW] = sA; ob[2*HW] = mG;
        ob[3*HW] = sG; ob[4*HW] = mO; ob[5*HW] = sO;
    }
}

// ---------------------------------------------------------------------------
// Kernel 2: conv1 + bn + relu + pool -> g_x1h/l (validated R13)
// ---------------------------------------------------------------------------
#define TPB1 480
__global__ __launch_bounds__(TPB1, 1) void conv1_kernel(
    const float* __restrict__ w1, const float* __restrict__ cb1,
    const float* __restrict__ g1, const float* __restrict__ bb1,
    const float* __restrict__ m1, const float* __restrict__ v1)
{
    __shared__ float sm[6528 + 3456 + 128];
    const int IW_ = 6528, IE_ = 9984;
    const int b = blockIdx.x, tid = threadIdx.x;

    {
        const float* src = g_inp6 + (size_t)b * 6 * HW;
        for (int i = tid; i < 6 * HW; i += TPB1) {
            int c = i >> 10; int rem = i & 1023;
            sm[c * 1088 + (rem >> 5) * 34 + (rem & 31)] = src[i];
        }
        for (int i = tid; i < 64 * 6 * 9; i += TPB1) {
            int oc = i / 54; int r = i - oc * 54;
            int c = r / 9; int t = r - c * 9;
            sm[IW_ + ((oc >> 1) * 6 + c) * 18 + t * 2 + (oc & 1)] = w1[oc * 126 + (c + 2) * 9 + t];
        }
        if (tid < 64) {
            const float* cst = g_cst + (size_t)b * 8;
            float extra = 0.f;
            #pragma unroll
            for (int j = 0; j < 8; ++j) {
                int ic = (j < 2) ? j : (j + 6);
                const float* wb = w1 + tid * 126 + ic * 9;
                float s9 = 0.f;
                #pragma unroll
                for (int t = 0; t < 9; ++t) s9 += wb[t];
                extra += cst[j] * s9;
            }
            float s = g1[tid] * rsqrtf(v1[tid] + 1e-5f);
            sm[IE_ + tid] = s;
            sm[IE_ + 64 + tid] = s * (extra + cb1[tid] - m1[tid]) + bb1[tid];
        }
    }
    __syncthreads();

    __nv_bfloat16* xoh = g_x1h + (size_t)b * 225 * 64;
    __nv_bfloat16* xol = g_x1l + (size_t)b * 225 * 64;
    #pragma unroll
    for (int itb = 0; itb < 2; ++itb) {
        int it = tid + itb * TPB1;
        int ocg = it / 60;
        int r = it - ocg * 60;
        int pr = r >> 2, pq = r & 3;
        int x0 = 8 * pq, r0 = 2 * pr;

        u64 acc[2][2][8];
        #pragma unroll
        for (int p = 0; p < 2; ++p)
            #pragma unroll
            for (int e = 0; e < 2; ++e)
                #pragma unroll
                for (int c = 0; c < 8; ++c) acc[p][e][c] = 0ull;

        for (int ch = 0; ch < 6; ++ch) {
            const float* ib = &sm[ch * 1088 + r0 * 34 + x0];
            const u64* wb0 = (const u64*)&sm[IW_ + ((ocg * 2) * 6 + ch) * 18];
            const u64* wb1 = (const u64*)&sm[IW_ + ((ocg * 2 + 1) * 6 + ch) * 18];
            #pragma unroll
            for (int ir = 0; ir < 4; ++ir) {
                u64 d[10];
                #pragma unroll
                for (int q = 0; q < 5; ++q) {
                    float2 a = *(const float2*)(ib + ir * 34 + 2 * q);
                    d[2*q] = dup2f(a.x); d[2*q+1] = dup2f(a.y);
                }
                #pragma unroll
                for (int kx = 0; kx < 3; ++kx) {
                    if (ir <= 2) {
                        u64 wa = wb0[ir*3+kx], wc = wb1[ir*3+kx];
                        #pragma unroll
                        for (int c = 0; c < 8; ++c) { fma2(acc[0][0][c], wa, d[c+kx]); fma2(acc[1][0][c], wc, d[c+kx]); }
                    }
                    if (ir >= 1) {
                        u64 wa = wb0[(ir-1)*3+kx], wc = wb1[(ir-1)*3+kx];
                        #pragma unroll
                        for (int c = 0; c < 8; ++c) { fma2(acc[0][1][c], wa, d[c+kx]); fma2(acc[1][1][c], wc, d[c+kx]); }
                    }
                }
            }
        }
        #pragma unroll
        for (int p = 0; p < 2; ++p) {
            int oc0 = ocg * 4 + 2 * p;
            float s0 = sm[IE_+oc0], bi0 = sm[IE_+64+oc0];
            float s1 = sm[IE_+oc0+1], bi1 = sm[IE_+64+oc0+1];
            #pragma unroll
            for (int j = 0; j < 4; ++j) {
                int pt = 4 * pq + j;
                if (pt < 15) {
                    float2 a = unp2(acc[p][0][2*j]), bq = unp2(acc[p][0][2*j+1]);
                    float2 cq = unp2(acc[p][1][2*j]), e = unp2(acc[p][1][2*j+1]);
                    float v0 = fmaxf(fmaxf(fmaxf(s0*a.x+bi0,0.f), fmaxf(s0*bq.x+bi0,0.f)),
                                     fmaxf(fmaxf(s0*cq.x+bi0,0.f), fmaxf(s0*e.x+bi0,0.f)));
                    float v1_ = fmaxf(fmaxf(fmaxf(s1*a.y+bi1,0.f), fmaxf(s1*bq.y+bi1,0.f)),
                                      fmaxf(fmaxf(s1*cq.y+bi1,0.f), fmaxf(s1*e.y+bi1,0.f)));
                    int pos = pr * 15 + pt;
                    __nv_bfloat16 h0 = __float2bfloat16(v0), h1 = __float2bfloat16(v1_);
                    *(unsigned*)&xoh[pos * 64 + oc0] =
                        (unsigned)__bfloat16_as_ushort(h0) | ((unsigned)__bfloat16_as_ushort(h1) << 16);
                    *(unsigned*)&xol[pos * 64 + oc0] =
                        pack2bf(v0 - __bfloat162float(h0), v1_ - __bfloat162float(h1));
                }
            }
        }
    }
}

// ---------------------------------------------------------------------------
// Kernel 3/4: conv 64->64 as 9 tap-GEMMs, bf16 3-pass, N-SPLIT across
// blockIdx.y (2 CTAs per image -> 2 CTAs/SM). Half-width W (LDW=40)
// streamed hi+lo in 4-tap chunks.
// ---------------------------------------------------------------------------
template<int IN_W, int OUT_W, bool FP32OUT, int TPB>
__global__ __launch_bounds__(TPB, 2) void convmma_kernel(
    const __nv_bfloat16* __restrict__ xinh, const __nv_bfloat16* __restrict__ xinl,
    __nv_bfloat16* __restrict__ xouth, __nv_bfloat16* __restrict__ xoutl,
    float* __restrict__ xoutf,
    int woff,
    const float* __restrict__ cb,
    const float* __restrict__ gg, const float* __restrict__ bbv,
    const float* __restrict__ mmv, const float* __restrict__ vvv)
{
    constexpr int INROWS = IN_W * IN_W;
    constexpr int MMAX = (OUT_W - 1) * IN_W + OUT_W;
    constexpr int MTILES = (MMAX + 15) / 16;
    constexpr int XROWS = ((MTILES * 16 + 2 * IN_W + 2 + 15) / 16) * 16;
    constexpr int LDX = 72, LDW = 40;
    constexpr int OXH = 0;
    constexpr int OXL = OXH + XROWS * LDX * 2;
    constexpr int OWB = OXL + XROWS * LDX * 2;
    constexpr int OSB = OWB + 4 * 2 * 64 * LDW * 2;   // W chunk buffer 40960 B

    extern __shared__ char smc[];
    __nv_bfloat16* Xh = (__nv_bfloat16*)(smc + OXH);
    __nv_bfloat16* Xl = (__nv_bfloat16*)(smc + OXL);
    __nv_bfloat16* Wb = (__nv_bfloat16*)(smc + OWB);
    float* sbs = (float*)(smc + OSB);

    const int b = blockIdx.x, nh = blockIdx.y;
    const int tid = threadIdx.x, wid = tid >> 5, lane = tid & 31;

    // X hi/lo into smem — vectorized
    {
        const uint4* sh = (const uint4*)(xinh + (size_t)b * INROWS * 64);
        const uint4* sl = (const uint4*)(xinl + (size_t)b * INROWS * 64);
        for (int i = tid; i < INROWS * 8; i += TPB) {
            int p = i >> 3, c8 = (i & 7) * 8;
            *(uint4*)&Xh[p * LDX + c8] = sh[i];
            *(uint4*)&Xl[p * LDX + c8] = sl[i];
        }
        uint4 z = make_uint4(0, 0, 0, 0);
        for (int i = tid; i < (XROWS - INROWS) * 8; i += TPB) {
            int p = INROWS + (i >> 3), c8 = (i & 7) * 8;
            *(uint4*)&Xh[p * LDX + c8] = z;
            *(uint4*)&Xl[p * LDX + c8] = z;
        }
    }
    if (tid < 64) {
        float s = gg[tid] * rsqrtf(vvv[tid] + 1e-5f);
        sbs[tid] = s;
        sbs[64 + tid] = s * (cb[tid] - mmv[tid]) + bbv[tid];
    }

    const int mt = wid;

    wmma::fragment<wmma::accumulator, 16, 16, 16, float> P[2], Q[2];
    wmma::fill_fragment(P[0], 0.f); wmma::fill_fragment(P[1], 0.f);
    wmma::fill_fragment(Q[0], 0.f); wmma::fill_fragment(Q[1], 0.f);

    for (int c0 = 0; c0 < 9; c0 += 4) {
        const int ntaps = (9 - c0 < 4) ? (9 - c0) : 4;
        __syncthreads();   // Wb free / first: orders X writes
        for (int i = tid; i < ntaps * 512; i += TPB) {
            int tt = i >> 9, rr = i & 511;
            int s = rr >> 8, r2 = rr & 255;
            int ic = r2 >> 2, q = r2 & 3;
            const uint4* src = (const uint4*)((s ? g_wl : g_wh) + woff);
            uint4 v = src[(c0 + tt) * 512 + ic * 8 + nh * 4 + q];
            *(uint4*)&Wb[((tt * 2 + s) * 64 + ic) * LDW + q * 8] = v;
        }
        __syncthreads();

        #pragma unroll 1
        for (int tt = 0; tt < ntaps; ++tt) {
            int tap = c0 + tt;
            int toff = (tap / 3) * IN_W + (tap - (tap / 3) * 3);
            const __nv_bfloat16* A0 = Xh + (mt * 16 + toff) * LDX;
            const __nv_bfloat16* A1 = Xl + (mt * 16 + toff) * LDX;
            const __nv_bfloat16* Bh = Wb + ((tt * 2 + 0) * 64) * LDW;
            const __nv_bfloat16* Bl = Wb + ((tt * 2 + 1) * 64) * LDW;
            #pragma unroll
            for (int k = 0; k < 4; ++k) {
                wmma::fragment<wmma::matrix_a, 16, 16, 16, __nv_bfloat16, wmma::row_major> ah, al;
                wmma::load_matrix_sync(ah, A0 + k * 16, LDX);
                wmma::load_matrix_sync(al, A1 + k * 16, LDX);
                #pragma unroll
                for (int nt = 0; nt < 2; ++nt) {
                    wmma::fragment<wmma::matrix_b, 16, 16, 16, __nv_bfloat16, wmma::row_major> bh, bl;
                    wmma::load_matrix_sync(bh, Bh + k * 16 * LDW + nt * 16, LDW);
                    wmma::load_matrix_sync(bl, Bl + k * 16 * LDW + nt * 16, LDW);
                    wmma::mma_sync(P[nt], ah, bh, P[nt]);
                    wmma::mma_sync(Q[nt], al, bh, Q[nt]);
                    wmma::mma_sync(Q[nt], ah, bl, Q[nt]);
                }
            }
        }
    }

    #pragma unroll
    for (int nt = 0; nt < 2; ++nt)
        #pragma unroll
        for (int i = 0; i < P[nt].num_elements; ++i)
            P[nt].x[i] += Q[nt].x[i];

    // ---- epilogue (patch aliases X @0; all X reads done) ----
    __syncthreads();
    float* patch = (float*)(smc) + wid * 16 * 36;
    wmma::store_matrix_sync(patch,      P[0], 36, wmma::mem_row_major);
    wmma::store_matrix_sync(patch + 16, P[1], 36, wmma::mem_row_major);
    __syncwarp();
    {
        int r = lane & 15, ch = (lane >> 4) * 16;
        int p = mt * 16 + r;
        int y = p / IN_W, x = p - y * IN_W;
        if (y < OUT_W && x < OUT_W) {
            int orow = y * OUT_W + x;
            int cg = nh * 32 + ch;
            if (FP32OUT) {
                float4 f[4];
                #pragma unroll
                for (int q = 0; q < 4; ++q) {
                    float vv[4];
                    #pragma unroll
                    for (int j = 0; j < 4; ++j) {
                        int c = cg + 4 * q + j;
                        vv[j] = fmaxf(sbs[c] * patch[r * 36 + ch + 4*q + j] + sbs[64 + c], 0.f);
                    }
                    f[q] = make_float4(vv[0], vv[1], vv[2], vv[3]);
                }
                float4* d = (float4*)&xoutf[(size_t)b * OUT_W * OUT_W * 64 + orow * 64 + cg];
                d[0] = f[0]; d[1] = f[1]; d[2] = f[2]; d[3] = f[3];
            } else {
                unsigned uh[8], ul[8];
                #pragma unroll
                for (int q = 0; q < 8; ++q) {
                    int c = cg + 2 * q;
                    float v0 = fmaxf(sbs[c] * patch[r * 36 + ch + 2*q] + sbs[64 + c], 0.f);
                    float v1_ = fmaxf(sbs[c+1] * patch[r * 36 + ch + 2*q + 1] + sbs[64 + c + 1], 0.f);
                    __nv_bfloat16 h0 = __float2bfloat16(v0), h1 = __float2bfloat16(v1_);
                    uh[q] = (unsigned)__bfloat16_as_ushort(h0) | ((unsigned)__bfloat16_as_ushort(h1) << 16);
                    ul[q] = pack2bf(v0 - __bfloat162float(h0), v1_ - __bfloat162float(h1));
                }
                uint4* dh = (uint4*)&xouth[(size_t)b * OUT_W * OUT_W * 64 + orow * 64 + cg];
                uint4* dl = (uint4*)&xoutl[(size_t)b * OUT_W * OUT_W * 64 + orow * 64 + cg];
                dh[0] = make_uint4(uh[0], uh[1], uh[2], uh[3]);
                dh[1] = make_uint4(uh[4], uh[5], uh[6], uh[7]);
                dl[0] = make_uint4(ul[0], ul[1], ul[2], ul[3]);
                dl[1] = make_uint4(ul[4], ul[5], ul[6], ul[7]);
            }
        }
    }
}

// ---------------------------------------------------------------------------
// Kernel 5: conv4 (64->1, 11x11 -> 9x9) + global max (validated R9 shape)
// ---------------------------------------------------------------------------
__global__ __launch_bounds__(128) void conv4_kernel(
    const float* __restrict__ w4, const float* __restrict__ cb4, float* __restrict__ out)
{
    __shared__ float xs[121 * 68];
    __shared__ float ws[576];
    __shared__ float red[4];
    const int b = blockIdx.x, tid = threadIdx.x;
    const float* src = g_x3 + (size_t)b * 121 * 64;
    for (int i = tid; i < 121 * 64; i += 128) xs[(i >> 6) * 68 + (i & 63)] = src[i];
    for (int i = tid; i < 576; i += 128) ws[i] = w4[i];
    __syncthreads();

    float lm = -INFINITY;
    if (tid < 81) {
        int y = tid / 9, x = tid - (tid / 9) * 9;
        float a = 0.f;
        #pragma unroll
        for (int ky = 0; ky < 3; ++ky)
            #pragma unroll
            for (int kx = 0; kx < 3; ++kx) {
                const float* row = xs + ((y + ky) * 11 + (x + kx)) * 68;
                int t = ky * 3 + kx;
                for (int ic = 0; ic < 64; ++ic)
                    a += row[ic] * ws[ic * 9 + t];
            }
        lm = a;
    }
    #pragma unroll
    for (int off = 16; off > 0; off >>= 1) lm = fmaxf(lm, __shfl_xor_sync(0xffffffffu, lm, off));
    if ((tid & 31) == 0) red[tid >> 5] = lm;
    __syncthreads();
    if (tid == 0) {
        float v = fmaxf(fmaxf(red[0], red[1]), fmaxf(red[2], red[3]));
        out[b] = v + cb4[0];
    }
}

// ---------------------------------------------------------------------------
extern "C" void kernel_launch(void* const* d_in, const int* in_sizes, int n_in,
                              void* d_out, int out_size)
{
    // conv2: X 69120 + Wb 40960 + sbs 512 = 110592 (2 CTAs/SM)
    // conv3: X 50688 + Wb 40960 + sbs 512 = 92160  (2 CTAs/SM)
    const int S2 = 110592;
    const int S3 = 92160;
    static __nv_bfloat16 *x1h = nullptr, *x1l = nullptr, *x2h = nullptr, *x2l = nullptr;
    static float* x3 = nullptr;
    if (!x1h) {
        cudaGetSymbolAddress((void**)&x1h, g_x1h);
        cudaGetSymbolAddress((void**)&x1l, g_x1l);
        cudaGetSymbolAddress((void**)&x2h, g_x2h);
        cudaGetSymbolAddress((void**)&x2l, g_x2l);
        cudaGetSymbolAddress((void**)&x3, g_x3);
        cudaFuncSetAttribute(convmma_kernel<15,13,false,416>, cudaFuncAttributeMaxDynamicSharedMemorySize, S2);
        cudaFuncSetAttribute(convmma_kernel<13,11,true,288>,  cudaFuncAttributeMaxDynamicSharedMemorySize, S3);
    }

    wprep_kernel<<<288, 256>>>((const float*)d_in[11], (const float*)d_in[17]);

    stats_kernel<<<BTOT, 1024>>>(
        (const float*)d_in[0], (const float*)d_in[1],
        (const float*)d_in[2], (const float*)d_in[3], d_in[4]);

    conv1_kernel<<<BTOT, TPB1>>>(
        (const float*)d_in[5],  (const float*)d_in[6],
        (const float*)d_in[7],  (const float*)d_in[8],
        (const float*)d_in[9],  (const float*)d_in[10]);

    convmma_kernel<15,13,false,416><<<dim3(BTOT, 2), 416, S2>>>(
        x1h, x1l, x2h, x2l, nullptr, 0,
        (const float*)d_in[12],
        (const float*)d_in[13], (const float*)d_in[14],
        (const float*)d_in[15], (const float*)d_in[16]);

    convmma_kernel<13,11,true,288><<<dim3(BTOT, 2), 288, S3>>>(
        x2h, x2l, nullptr, nullptr, x3, 36864,
        (const float*)d_in[18],
        (const float*)d_in[19], (const float*)d_in[20],
        (const float*)d_in[21], (const float*)d_in[22]);

    conv4_kernel<<<BTOT, 128>>>(
        (const float*)d_in[23], (const float*)d_in[24], (float*)d_out);
}